// round 2
// baseline (speedup 1.0000x reference)
#include <cuda_runtime.h>
#include <math.h>

#define TT 512      // sequence length
#define DD 512      // model dim
#define LOG2E 1.4426950408889634f

// Scratch (allocation-free rule: device globals)
__device__ float g_qkv[3 * DD * TT];   // [w][o][t]  w=0:q 1:k 2:v
__device__ float g_ao[DD * TT];        // attention output [o][t]

__device__ __forceinline__ float fast_ex2(float x) {
    float r;
    asm("ex2.approx.ftz.f32 %0, %1;" : "=f"(r) : "f"(x));
    return r;
}

// ---------------------------------------------------------------------------
// GEMM 1: fused QKV projection.
// C[n][m] = sum_k W[n%512][k] * X[m][k],  n in [0,1536), m=t in [0,512)
// 32(m) x 32(n) block tile, BK=16, 64 threads, 4x4 outputs/thread,
// register-prefetched global loads, float4 smem reads.
// ---------------------------------------------------------------------------
__global__ void qkv_gemm_kernel(const float* __restrict__ x,
                                const float* __restrict__ Wq,
                                const float* __restrict__ Wk,
                                const float* __restrict__ Wv) {
    __shared__ float Xs[16][36];  // [k][m], pad 36 (144B row -> float4-aligned)
    __shared__ float Ws[16][36];  // [k][n]

    const int m0 = blockIdx.x * 32;
    const int n0 = blockIdx.y * 32;
    const float* W = (n0 < 512) ? Wq : (n0 < 1024 ? Wk : Wv);
    const int nb = n0 & 511;

    const int tid = threadIdx.x;   // 0..63
    const int row = tid & 31;      // load row (warp-uniform kc -> conflict-free STS)
    const int kc  = (tid >> 5) * 8;
    const int tx  = tid & 7;       // m group
    const int ty  = tid >> 3;      // n group

    const float* xg = &x[(m0 + row) * DD + kc];
    const float* wg = &W[(nb + row) * DD + kc];

    float4 xa = *(const float4*)(xg);
    float4 xb = *(const float4*)(xg + 4);
    float4 wa = *(const float4*)(wg);
    float4 wb = *(const float4*)(wg + 4);

    float acc[4][4] = {};

    for (int k0 = 0; k0 < DD; k0 += 16) {
        // commit current regs to smem (transposed)
        Xs[kc + 0][row] = xa.x; Xs[kc + 1][row] = xa.y;
        Xs[kc + 2][row] = xa.z; Xs[kc + 3][row] = xa.w;
        Xs[kc + 4][row] = xb.x; Xs[kc + 5][row] = xb.y;
        Xs[kc + 6][row] = xb.z; Xs[kc + 7][row] = xb.w;
        Ws[kc + 0][row] = wa.x; Ws[kc + 1][row] = wa.y;
        Ws[kc + 2][row] = wa.z; Ws[kc + 3][row] = wa.w;
        Ws[kc + 4][row] = wb.x; Ws[kc + 5][row] = wb.y;
        Ws[kc + 6][row] = wb.z; Ws[kc + 7][row] = wb.w;
        __syncthreads();

        if (k0 + 16 < DD) {   // prefetch next K-tile into regs
            xa = *(const float4*)(xg + k0 + 16);
            xb = *(const float4*)(xg + k0 + 20);
            wa = *(const float4*)(wg + k0 + 16);
            wb = *(const float4*)(wg + k0 + 20);
        }

#pragma unroll
        for (int kk = 0; kk < 16; kk++) {
            float4 a = *(const float4*)&Xs[kk][tx * 4];
            float4 b = *(const float4*)&Ws[kk][ty * 4];
            acc[0][0] += a.x * b.x; acc[0][1] += a.x * b.y;
            acc[0][2] += a.x * b.z; acc[0][3] += a.x * b.w;
            acc[1][0] += a.y * b.x; acc[1][1] += a.y * b.y;
            acc[1][2] += a.y * b.z; acc[1][3] += a.y * b.w;
            acc[2][0] += a.z * b.x; acc[2][1] += a.z * b.y;
            acc[2][2] += a.z * b.z; acc[2][3] += a.z * b.w;
            acc[3][0] += a.w * b.x; acc[3][1] += a.w * b.y;
            acc[3][2] += a.w * b.z; acc[3][3] += a.w * b.w;
        }
        __syncthreads();
    }

    // C[n][m]: per j (n), contiguous float4 over i (m)
#pragma unroll
    for (int j = 0; j < 4; j++) {
        float4 o = make_float4(acc[0][j], acc[1][j], acc[2][j], acc[3][j]);
        *(float4*)&g_qkv[(n0 + ty * 4 + j) * TT + m0 + tx * 4] = o;
    }
}

// ---------------------------------------------------------------------------
// RoPE (rotation across the HEADS axis, per reference's rotate_half on axis=1)
// One thread per (c, t); handles all 8 heads of q and k in place.
// ---------------------------------------------------------------------------
__global__ void rope_kernel() {
    const int gid = blockIdx.x * blockDim.x + threadIdx.x;  // 0..32767
    const int t = gid & 511;
    const int c = gid >> 9;      // 0..63
    const int fi = c & 31;

    // Match jnp fp32 table: invf = fp32(10000^(-2*fi/64)); ang = fp32(t)*invf
    float invf = (float)pow(10000.0, -(double)(2 * fi) / 64.0);
    float ang = (float)t * invf;
    float cv = (float)cos((double)ang);
    float sv = (float)sin((double)ang);

#pragma unroll
    for (int w = 0; w < 2; w++) {            // q then k
        float* base = g_qkv + w * DD * TT;
        float vals[8];
#pragma unroll
        for (int h = 0; h < 8; h++) vals[h] = base[(h * 64 + c) * TT + t];
#pragma unroll
        for (int h = 0; h < 8; h++) {
            float rot = (h < 4) ? -vals[h + 4] : vals[h - 4];
            base[(h * 64 + c) * TT + t] = vals[h] * cv + rot * sv;
        }
    }
}

// ---------------------------------------------------------------------------
// Per-channel causal softmax attention.
// Channel c: out[i] = sum_{j<=i} softmax_j(q[i]*k[j]*scale) * v[j]
// Scores are O(few) in magnitude -> no max subtraction needed in fp32.
// One block per channel; thread tid handles queries i=tid and i=511-tid.
// ---------------------------------------------------------------------------
__global__ void attn_kernel() {
    const int c = blockIdx.x;  // 0..511
    const float* q = g_qkv + 0 * DD * TT + c * TT;
    const float* k = g_qkv + 1 * DD * TT + c * TT;
    const float* v = g_qkv + 2 * DD * TT + c * TT;

    __shared__ float ks[512];
    __shared__ float vs[512];
    const int tid = threadIdx.x;  // 0..255
    ks[tid]       = k[tid];
    ks[tid + 256] = k[tid + 256];
    vs[tid]       = v[tid];
    vs[tid + 256] = v[tid + 256];
    __syncthreads();

#pragma unroll
    for (int rep = 0; rep < 2; rep++) {
        const int i = rep ? (511 - tid) : tid;
        const float qs = q[i] * (0.125f * LOG2E);  // scale=1/sqrt(64), log2e folded
        float l = 0.f, acc = 0.f;
#pragma unroll 4
        for (int j = 0; j <= i; j++) {
            float p = fast_ex2(qs * ks[j]);
            l += p;
            acc += p * vs[j];
        }
        g_ao[c * TT + i] = acc / l;
    }
}

// ---------------------------------------------------------------------------
// GEMM 2: output projection.
// y[m][n] = sum_k Wo[n][k] * A[k][m]   (A = g_ao [o][t]: k=o rows, m=t cols)
// Same tiling as qkv; A tile loads need no transpose.
// ---------------------------------------------------------------------------
__global__ void out_gemm_kernel(const float* __restrict__ Wo,
                                float* __restrict__ y) {
    __shared__ float As[16][36];  // [k][m]
    __shared__ float Ws[16][36];  // [k][n]

    const int m0 = blockIdx.x * 32;  // t
    const int n0 = blockIdx.y * 32;  // o

    const int tid = threadIdx.x;     // 0..63
    // A load mapping: direct [k][m] rows
    const int akr = tid >> 2;        // 0..15 (k row)
    const int amc = (tid & 3) * 8;   // m col
    // W load mapping: transpose
    const int row = tid & 31;
    const int kc  = (tid >> 5) * 8;
    const int tx  = tid & 7;
    const int ty  = tid >> 3;

    const float* ag = &g_ao[akr * TT + m0 + amc];
    const float* wg = &Wo[(n0 + row) * DD + kc];

    float4 aa = *(const float4*)(ag);
    float4 ab = *(const float4*)(ag + 4);
    float4 wa = *(const float4*)(wg);
    float4 wb = *(const float4*)(wg + 4);

    float acc[4][4] = {};

    for (int k0 = 0; k0 < DD; k0 += 16) {
        *(float4*)&As[akr][amc]     = aa;
        *(float4*)&As[akr][amc + 4] = ab;
        Ws[kc + 0][row] = wa.x; Ws[kc + 1][row] = wa.y;
        Ws[kc + 2][row] = wa.z; Ws[kc + 3][row] = wa.w;
        Ws[kc + 4][row] = wb.x; Ws[kc + 5][row] = wb.y;
        Ws[kc + 6][row] = wb.z; Ws[kc + 7][row] = wb.w;
        __syncthreads();

        if (k0 + 16 < DD) {
            aa = *(const float4*)(ag + (k0 + 16) * TT);
            ab = *(const float4*)(ag + (k0 + 16) * TT + 4);
            wa = *(const float4*)(wg + k0 + 16);
            wb = *(const float4*)(wg + k0 + 20);
        }

#pragma unroll
        for (int kk = 0; kk < 16; kk++) {
            float4 a = *(const float4*)&As[kk][tx * 4];
            float4 b = *(const float4*)&Ws[kk][ty * 4];
            acc[0][0] += a.x * b.x; acc[0][1] += a.x * b.y;
            acc[0][2] += a.x * b.z; acc[0][3] += a.x * b.w;
            acc[1][0] += a.y * b.x; acc[1][1] += a.y * b.y;
            acc[1][2] += a.y * b.z; acc[1][3] += a.y * b.w;
            acc[2][0] += a.z * b.x; acc[2][1] += a.z * b.y;
            acc[2][2] += a.z * b.z; acc[2][3] += a.z * b.w;
            acc[3][0] += a.w * b.x; acc[3][1] += a.w * b.y;
            acc[3][2] += a.w * b.z; acc[3][3] += a.w * b.w;
        }
        __syncthreads();
    }

    // y[m][n]: per i (m), contiguous float4 over j (n)
#pragma unroll
    for (int i = 0; i < 4; i++) {
        float4 o = make_float4(acc[i][0], acc[i][1], acc[i][2], acc[i][3]);
        *(float4*)&y[(m0 + tx * 4 + i) * DD + n0 + ty * 4] = o;
    }
}

// ---------------------------------------------------------------------------
extern "C" void kernel_launch(void* const* d_in, const int* in_sizes, int n_in,
                              void* d_out, int out_size) {
    const float* x  = (const float*)d_in[0];
    const float* Wq = (const float*)d_in[1];
    const float* Wk = (const float*)d_in[2];
    const float* Wv = (const float*)d_in[3];
    const float* Wo = (const float*)d_in[4];
    float* y = (float*)d_out;

    qkv_gemm_kernel<<<dim3(512 / 32, 1536 / 32), 64>>>(x, Wq, Wk, Wv);
    rope_kernel<<<128, 256>>>();
    attn_kernel<<<512, 256>>>();
    out_gemm_kernel<<<dim3(512 / 32, 512 / 32), 64>>>(Wo, y);
}

// round 3
// speedup vs baseline: 1.1560x; 1.1560x over previous
#include <cuda_runtime.h>
#include <math.h>

#define TT 512      // sequence length
#define DD 512      // model dim
#define LOG2E 1.4426950408889634f

// Scratch (allocation-free rule: device globals)
__device__ float g_qkv[3 * DD * TT];   // [w][o][t]  w=0:q 1:k 2:v  (pre-RoPE)
__device__ float g_ao[DD * TT];        // attention output [o][t]

__device__ __forceinline__ float fast_ex2(float x) {
    float r;
    asm("ex2.approx.ftz.f32 %0, %1;" : "=f"(r) : "f"(x));
    return r;
}

// ---------------------------------------------------------------------------
// GEMM 1: fused QKV projection.
// C[n][m] = sum_k W[n%512][k] * X[m][k],  n in [0,1536), m=t in [0,512)
// 32(m) x 64(n) tile, BK=16, 128 threads (4 warps), 4x4 outputs/thread.
// ---------------------------------------------------------------------------
__global__ void __launch_bounds__(128) qkv_gemm_kernel(
        const float* __restrict__ x,
        const float* __restrict__ Wq,
        const float* __restrict__ Wk,
        const float* __restrict__ Wv) {
    __shared__ float Xs[16][36];  // [k][m]
    __shared__ float Ws[16][68];  // [k][n]

    const int m0 = blockIdx.x * 32;
    const int n0 = blockIdx.y * 64;
    const float* W = (n0 < 512) ? Wq : (n0 < 1024 ? Wk : Wv);
    const int nb = n0 & 511;

    const int tid = threadIdx.x;     // 0..127
    const int lr  = tid & 31;        // load row
    const int lc  = (tid >> 5) * 4;  // load k-col (0,4,8,12)
    const int tx  = tid & 7;         // m group (x4)
    const int ty  = tid >> 3;        // n group (x4), 0..15

    const float* xg = &x[(m0 + lr) * DD + lc];
    const float* wg0 = &W[(nb + lr) * DD + lc];
    const float* wg1 = &W[(nb + lr + 32) * DD + lc];

    float4 xa = *(const float4*)(xg);
    float4 wa = *(const float4*)(wg0);
    float4 wb = *(const float4*)(wg1);

    float acc[4][4] = {};

    for (int k0 = 0; k0 < DD; k0 += 16) {
        // commit current regs to smem (transposed)
        Xs[lc + 0][lr] = xa.x; Xs[lc + 1][lr] = xa.y;
        Xs[lc + 2][lr] = xa.z; Xs[lc + 3][lr] = xa.w;
        Ws[lc + 0][lr] = wa.x; Ws[lc + 1][lr] = wa.y;
        Ws[lc + 2][lr] = wa.z; Ws[lc + 3][lr] = wa.w;
        Ws[lc + 0][lr + 32] = wb.x; Ws[lc + 1][lr + 32] = wb.y;
        Ws[lc + 2][lr + 32] = wb.z; Ws[lc + 3][lr + 32] = wb.w;
        __syncthreads();

        if (k0 + 16 < DD) {   // prefetch next K-tile into regs
            xa = *(const float4*)(xg + k0 + 16);
            wa = *(const float4*)(wg0 + k0 + 16);
            wb = *(const float4*)(wg1 + k0 + 16);
        }

#pragma unroll
        for (int kk = 0; kk < 16; kk++) {
            float4 a = *(const float4*)&Xs[kk][tx * 4];
            float4 b = *(const float4*)&Ws[kk][ty * 4];
            acc[0][0] += a.x * b.x; acc[0][1] += a.x * b.y;
            acc[0][2] += a.x * b.z; acc[0][3] += a.x * b.w;
            acc[1][0] += a.y * b.x; acc[1][1] += a.y * b.y;
            acc[1][2] += a.y * b.z; acc[1][3] += a.y * b.w;
            acc[2][0] += a.z * b.x; acc[2][1] += a.z * b.y;
            acc[2][2] += a.z * b.z; acc[2][3] += a.z * b.w;
            acc[3][0] += a.w * b.x; acc[3][1] += a.w * b.y;
            acc[3][2] += a.w * b.z; acc[3][3] += a.w * b.w;
        }
        __syncthreads();
    }

    // C[n][m]: per j (n), contiguous float4 over i (m)
#pragma unroll
    for (int j = 0; j < 4; j++) {
        float4 o = make_float4(acc[0][j], acc[1][j], acc[2][j], acc[3][j]);
        *(float4*)&g_qkv[(n0 + ty * 4 + j) * TT + m0 + tx * 4] = o;
    }
}

// ---------------------------------------------------------------------------
// Attention with fused RoPE.
// Block c = h*64 + ch handles one (head, channel) row.
// RoPE (rotate across HEADS axis): h<4: rot = -row(h+4,ch); h>=4: +row(h-4,ch)
// out[i] = sum_{j<=i} softmax_j(qr[i]*kr[j]*scale) * v[j]
// ---------------------------------------------------------------------------
__global__ void __launch_bounds__(256) attn_kernel() {
    const int c  = blockIdx.x;       // 0..511
    const int h  = c >> 6;
    const int ch = c & 63;
    const int fi = ch & 31;
    const int pc = ((h < 4) ? (h + 4) : (h - 4)) * 64 + ch;  // partner row
    const float sgn = (h < 4) ? -1.0f : 1.0f;

    const float* q  = g_qkv + 0 * DD * TT + c  * TT;
    const float* qp = g_qkv + 0 * DD * TT + pc * TT;
    const float* k  = g_qkv + 1 * DD * TT + c  * TT;
    const float* kp = g_qkv + 1 * DD * TT + pc * TT;
    const float* v  = g_qkv + 2 * DD * TT + c  * TT;

    __shared__ float ks[512];
    __shared__ float vs[512];
    __shared__ float cs[512];
    __shared__ float sn[512];
    __shared__ float s_invf;

    const int tid = threadIdx.x;  // 0..255
    if (tid == 0) {
        // match jnp fp32 table: invf = fp32(10000^(-2*fi/64))
        s_invf = (float)pow(10000.0, -(double)(2 * fi) / 64.0);
    }
    __syncthreads();
    const float invf = s_invf;

#pragma unroll
    for (int off = 0; off < 512; off += 256) {
        const int t = tid + off;
        float sv, cv;
        sincosf((float)t * invf, &sv, &cv);
        cs[t] = cv;
        sn[t] = sv;
        ks[t] = k[t] * cv + sgn * kp[t] * sv;   // rotated k
        vs[t] = v[t];
    }
    __syncthreads();

#pragma unroll
    for (int rep = 0; rep < 2; rep++) {
        const int i = rep ? (511 - tid) : tid;
        const float qr = q[i] * cs[i] + sgn * qp[i] * sn[i];
        const float qs = qr * (0.125f * LOG2E);  // scale=1/sqrt(64), log2e folded
        float l = 0.f, acc = 0.f;
#pragma unroll 4
        for (int j = 0; j <= i; j++) {
            float p = fast_ex2(qs * ks[j]);
            l += p;
            acc += p * vs[j];
        }
        g_ao[c * TT + i] = acc / l;
    }
}

// ---------------------------------------------------------------------------
// GEMM 2: output projection.
// y[m][n] = sum_k Wo[n][k] * A[k][m]   (A = g_ao [o][t]: k=o rows, m=t cols)
// 32(m) x 64(n) tile, BK=16, 128 threads, 4x4 outputs/thread.
// ---------------------------------------------------------------------------
__global__ void __launch_bounds__(128) out_gemm_kernel(
        const float* __restrict__ Wo,
        float* __restrict__ y) {
    __shared__ float As[16][36];  // [k][m]
    __shared__ float Ws[16][68];  // [k][n]

    const int m0 = blockIdx.x * 32;  // t
    const int n0 = blockIdx.y * 64;  // o

    const int tid = threadIdx.x;     // 0..127
    // A tile: [k][m] direct, 16x32 floats, 1 float4/thread
    const int akr = tid >> 3;        // 0..15 (k)
    const int amc = (tid & 7) * 4;   // m col
    // W tile: transpose, 64 rows
    const int lr  = tid & 31;
    const int lc  = (tid >> 5) * 4;
    const int tx  = tid & 7;
    const int ty  = tid >> 3;

    const float* ag  = &g_ao[akr * TT + m0 + amc];
    const float* wg0 = &Wo[(n0 + lr) * DD + lc];
    const float* wg1 = &Wo[(n0 + lr + 32) * DD + lc];

    float4 aa = *(const float4*)(ag);
    float4 wa = *(const float4*)(wg0);
    float4 wb = *(const float4*)(wg1);

    float acc[4][4] = {};

    for (int k0 = 0; k0 < DD; k0 += 16) {
        *(float4*)&As[akr][amc] = aa;
        Ws[lc + 0][lr] = wa.x; Ws[lc + 1][lr] = wa.y;
        Ws[lc + 2][lr] = wa.z; Ws[lc + 3][lr] = wa.w;
        Ws[lc + 0][lr + 32] = wb.x; Ws[lc + 1][lr + 32] = wb.y;
        Ws[lc + 2][lr + 32] = wb.z; Ws[lc + 3][lr + 32] = wb.w;
        __syncthreads();

        if (k0 + 16 < DD) {
            aa = *(const float4*)(ag + (k0 + 16) * TT);
            wa = *(const float4*)(wg0 + k0 + 16);
            wb = *(const float4*)(wg1 + k0 + 16);
        }

#pragma unroll
        for (int kk = 0; kk < 16; kk++) {
            float4 a = *(const float4*)&As[kk][tx * 4];
            float4 b = *(const float4*)&Ws[kk][ty * 4];
            acc[0][0] += a.x * b.x; acc[0][1] += a.x * b.y;
            acc[0][2] += a.x * b.z; acc[0][3] += a.x * b.w;
            acc[1][0] += a.y * b.x; acc[1][1] += a.y * b.y;
            acc[1][2] += a.y * b.z; acc[1][3] += a.y * b.w;
            acc[2][0] += a.z * b.x; acc[2][1] += a.z * b.y;
            acc[2][2] += a.z * b.z; acc[2][3] += a.z * b.w;
            acc[3][0] += a.w * b.x; acc[3][1] += a.w * b.y;
            acc[3][2] += a.w * b.z; acc[3][3] += a.w * b.w;
        }
        __syncthreads();
    }

    // y[m][n]: per i (m), contiguous float4 over j (n)
#pragma unroll
    for (int i = 0; i < 4; i++) {
        float4 o = make_float4(acc[i][0], acc[i][1], acc[i][2], acc[i][3]);
        *(float4*)&y[(m0 + tx * 4 + i) * DD + n0 + ty * 4] = o;
    }
}

// ---------------------------------------------------------------------------
extern "C" void kernel_launch(void* const* d_in, const int* in_sizes, int n_in,
                              void* d_out, int out_size) {
    const float* x  = (const float*)d_in[0];
    const float* Wq = (const float*)d_in[1];
    const float* Wk = (const float*)d_in[2];
    const float* Wv = (const float*)d_in[3];
    const float* Wo = (const float*)d_in[4];
    float* y = (float*)d_out;

    qkv_gemm_kernel<<<dim3(512 / 32, 1536 / 64), 128>>>(x, Wq, Wk, Wv);
    attn_kernel<<<512, 256>>>();
    out_gemm_kernel<<<dim3(512 / 32, 512 / 64), 128>>>(Wo, y);
}

// round 5
// speedup vs baseline: 1.3920x; 1.2042x over previous
#include <cuda_runtime.h>
#include <cuda_bf16.h>
#include <math.h>
#include <stdint.h>

#define TT 512
#define DD 512
#define LOG2E 1.4426950408889634f

// ---------------------------------------------------------------------------
// Device-global scratch (no allocations allowed)
// ---------------------------------------------------------------------------
__device__ float g_qkv[3 * DD * TT];            // [w][o][t] fp32 (GEMM1 out)
__device__ float g_ao[DD * TT];                 // attention out [o][t]
__device__ __nv_bfloat16 gAhi1[1536 * 512];     // W q,k,v stacked, hi
__device__ __nv_bfloat16 gAlo1[1536 * 512];     // lo residual
__device__ __nv_bfloat16 gBhi1[512 * 512];      // x [t][k]
__device__ __nv_bfloat16 gBlo1[512 * 512];
__device__ __nv_bfloat16 gWohi[512 * 512];      // Wo [o][d]
__device__ __nv_bfloat16 gWolo[512 * 512];
__device__ __nv_bfloat16 gaoThi[512 * 512];     // ao transposed [t][d]
__device__ __nv_bfloat16 gaoTlo[512 * 512];

__device__ __forceinline__ uint32_t smem_u32(const void* p) {
    uint32_t a;
    asm("{ .reg .u64 t; cvta.to.shared.u64 t, %1; cvt.u32.u64 %0, t; }"
        : "=r"(a) : "l"(p));
    return a;
}
__device__ __forceinline__ void cp16(uint32_t dst, const void* src) {
    asm volatile("cp.async.ca.shared.global [%0], [%1], 16;"
                 :: "r"(dst), "l"(src) : "memory");
}
__device__ __forceinline__ float fast_ex2(float x) {
    float r;
    asm("ex2.approx.ftz.f32 %0, %1;" : "=f"(r) : "f"(x));
    return r;
}

// mma.sync m16n8k16 row.col bf16 -> fp32 accumulate (baseline PTX, sm_80+)
#define MMA16816(c, a, b) \
    asm volatile( \
        "mma.sync.aligned.m16n8k16.row.col.f32.bf16.bf16.f32 " \
        "{%0,%1,%2,%3},{%4,%5,%6,%7},{%8,%9},{%0,%1,%2,%3};" \
        : "+f"((c)[0]), "+f"((c)[1]), "+f"((c)[2]), "+f"((c)[3]) \
        : "r"((a)[0]), "r"((a)[1]), "r"((a)[2]), "r"((a)[3]), \
          "r"((b)[0]), "r"((b)[1]))

// ---------------------------------------------------------------------------
// Split kernel: fp32 -> bf16 hi + bf16 lo(residual).
// Segments (each 65536 float4s): 0=Wq 1=Wk 2=Wv -> gA*1; 3=x -> gB*1; 4=Wo.
// ---------------------------------------------------------------------------
__global__ void __launch_bounds__(256) split_kernel(
        const float4* __restrict__ x,  const float4* __restrict__ Wq,
        const float4* __restrict__ Wk, const float4* __restrict__ Wv,
        const float4* __restrict__ Wo) {
    const int gid = blockIdx.x * 256 + threadIdx.x;   // 0..327679
    const int seg = gid >> 16;
    const int off = gid & 65535;

    const float4* src;
    __nv_bfloat16 *dh, *dl;
    switch (seg) {
        case 0: src = Wq; dh = gAhi1;          dl = gAlo1;          break;
        case 1: src = Wk; dh = gAhi1 + 262144; dl = gAlo1 + 262144; break;
        case 2: src = Wv; dh = gAhi1 + 524288; dl = gAlo1 + 524288; break;
        case 3: src = x;  dh = gBhi1;          dl = gBlo1;          break;
        default: src = Wo; dh = gWohi;          dl = gWolo;          break;
    }
    float4 v = src[off];
    __nv_bfloat16 h0 = __float2bfloat16(v.x), h1 = __float2bfloat16(v.y);
    __nv_bfloat16 h2 = __float2bfloat16(v.z), h3 = __float2bfloat16(v.w);
    __nv_bfloat16 l0 = __float2bfloat16(v.x - __bfloat162float(h0));
    __nv_bfloat16 l1 = __float2bfloat16(v.y - __bfloat162float(h1));
    __nv_bfloat16 l2 = __float2bfloat16(v.z - __bfloat162float(h2));
    __nv_bfloat16 l3 = __float2bfloat16(v.w - __bfloat162float(h3));
    __nv_bfloat162* oh = (__nv_bfloat162*)dh;
    __nv_bfloat162* ol = (__nv_bfloat162*)dl;
    __nv_bfloat162 a, b;
    a.x = h0; a.y = h1; b.x = h2; b.y = h3;
    oh[off * 2] = a; oh[off * 2 + 1] = b;
    a.x = l0; a.y = l1; b.x = l2; b.y = l3;
    ol[off * 2] = a; ol[off * 2 + 1] = b;
}

// ---------------------------------------------------------------------------
// bf16-split GEMM via mma.sync:
//   C[(m0+r)*512 + (n0+c)] = sum_k A[m0+r][k] * B[n0+c][k]
// CTA tile 64(m) x 64(n), 128 threads (4 warps, warp tile 32x32),
// K chunks of 64, cp.async double-buffered smem, padded rows (72 bf16).
// ---------------------------------------------------------------------------
#define ROWB 144                     // 72 bf16 per smem row (pad 8) = 144 bytes
#define MAT_B (64 * ROWB)            // one 64x64 bf16 matrix = 9216 bytes
#define BUF_B (4 * MAT_B)            // Ahi, Alo, Bhi, Blo = 36864 bytes
#define GEMM_SMEM (2 * BUF_B)        // 73728 bytes (double buffer)

__device__ __forceinline__ void gemm_body(
        const __nv_bfloat16* __restrict__ Ahi,
        const __nv_bfloat16* __restrict__ Alo,
        const __nv_bfloat16* __restrict__ Bhi,
        const __nv_bfloat16* __restrict__ Blo,
        float* __restrict__ C) {
    extern __shared__ char smem[];
    const uint32_t s0 = smem_u32(smem);

    const int tid = threadIdx.x;        // 0..127
    const int wid = tid >> 5;
    const int lane = tid & 31;
    const int g = lane >> 2;            // 0..7
    const int t = lane & 3;             // 0..3
    const int wm = (wid >> 1) * 32;     // warp m offset in tile
    const int wn = (wid & 1) * 32;      // warp n offset

    const int m0 = blockIdx.x * 64;
    const int n0 = blockIdx.y * 64;

    const uint4* A4h = (const uint4*)Ahi;
    const uint4* A4l = (const uint4*)Alo;
    const uint4* B4h = (const uint4*)Bhi;
    const uint4* B4l = (const uint4*)Blo;

    // load mapping: 512 uint4 per 64x64 matrix, 4 per thread
    const int lrow = tid >> 1;                  // 0..63 (two threads per row)
    const int lc0  = (tid & 1) * 4;             // first of 4 consecutive 16B units

    float acc[2][4][4] = {};

    // ---- chunk loader: chunk c into buffer b
    auto load_chunk = [&](int c, int b) {
        const uint32_t base = s0 + b * BUF_B;
#pragma unroll
        for (int i = 0; i < 4; i++) {
            const int c16 = lc0 + i;            // 0..7 within chunk row
            const uint32_t so = lrow * ROWB + c16 * 16;
            const size_t ga = (size_t)(m0 + lrow) * 64 + c * 8 + c16;
            const size_t gb = (size_t)(n0 + lrow) * 64 + c * 8 + c16;
            cp16(base + so,              A4h + ga);
            cp16(base + MAT_B + so,      A4l + ga);
            cp16(base + 2 * MAT_B + so,  B4h + gb);
            cp16(base + 3 * MAT_B + so,  B4l + gb);
        }
        asm volatile("cp.async.commit_group;" ::: "memory");
    };

    load_chunk(0, 0);

    for (int c = 0; c < 8; c++) {
        if (c < 7) {
            load_chunk(c + 1, (c + 1) & 1);
            asm volatile("cp.async.wait_group 1;" ::: "memory");
        } else {
            asm volatile("cp.async.wait_group 0;" ::: "memory");
        }
        __syncthreads();

        const char* sb = smem + (c & 1) * BUF_B;
        const char* sAh = sb;
        const char* sAl = sb + MAT_B;
        const char* sBh = sb + 2 * MAT_B;
        const char* sBl = sb + 3 * MAT_B;

#pragma unroll
        for (int ks = 0; ks < 4; ks++) {
            const int kO = ks * 32;             // 16 bf16 = 32 bytes
            uint32_t ah[2][4], al[2][4], bh[4][2], bl[4][2];
#pragma unroll
            for (int mt = 0; mt < 2; mt++) {
                const int r = wm + mt * 16 + g;
                const char* p0 = sAh + r * ROWB + kO + 4 * t;
                const char* p1 = sAl + r * ROWB + kO + 4 * t;
                ah[mt][0] = *(const uint32_t*)(p0);
                ah[mt][1] = *(const uint32_t*)(p0 + 8 * ROWB);
                ah[mt][2] = *(const uint32_t*)(p0 + 16);
                ah[mt][3] = *(const uint32_t*)(p0 + 8 * ROWB + 16);
                al[mt][0] = *(const uint32_t*)(p1);
                al[mt][1] = *(const uint32_t*)(p1 + 8 * ROWB);
                al[mt][2] = *(const uint32_t*)(p1 + 16);
                al[mt][3] = *(const uint32_t*)(p1 + 8 * ROWB + 16);
            }
#pragma unroll
            for (int nt = 0; nt < 4; nt++) {
                const int r = wn + nt * 8 + g;
                const char* p0 = sBh + r * ROWB + kO + 4 * t;
                const char* p1 = sBl + r * ROWB + kO + 4 * t;
                bh[nt][0] = *(const uint32_t*)(p0);
                bh[nt][1] = *(const uint32_t*)(p0 + 16);
                bl[nt][0] = *(const uint32_t*)(p1);
                bl[nt][1] = *(const uint32_t*)(p1 + 16);
            }
#pragma unroll
            for (int mt = 0; mt < 2; mt++)
#pragma unroll
                for (int nt = 0; nt < 4; nt++) {
                    MMA16816(acc[mt][nt], ah[mt], bh[nt]);
                    MMA16816(acc[mt][nt], ah[mt], bl[nt]);
                    MMA16816(acc[mt][nt], al[mt], bh[nt]);
                }
        }
        __syncthreads();
    }

    // epilogue: C fragment -> gmem (float2 per half-row)
#pragma unroll
    for (int mt = 0; mt < 2; mt++) {
        const int r = m0 + wm + mt * 16 + g;
#pragma unroll
        for (int nt = 0; nt < 4; nt++) {
            const int col = n0 + wn + nt * 8 + 2 * t;
            *(float2*)&C[(size_t)r * 512 + col] =
                make_float2(acc[mt][nt][0], acc[mt][nt][1]);
            *(float2*)&C[(size_t)(r + 8) * 512 + col] =
                make_float2(acc[mt][nt][2], acc[mt][nt][3]);
        }
    }
}

__global__ void __launch_bounds__(128) gemm1_kernel() {
    gemm_body(gAhi1, gAlo1, gBhi1, gBlo1, g_qkv);
}
__global__ void __launch_bounds__(128) gemm2_kernel(float* __restrict__ y) {
    gemm_body(gaoThi, gaoTlo, gWohi, gWolo, y);
}

// ---------------------------------------------------------------------------
// Attention with fused RoPE (rotation across HEADS axis).
// ---------------------------------------------------------------------------
__global__ void __launch_bounds__(256) attn_kernel() {
    const int c  = blockIdx.x;
    const int h  = c >> 6;
    const int ch = c & 63;
    const int fi = ch & 31;
    const int pc = ((h < 4) ? (h + 4) : (h - 4)) * 64 + ch;
    const float sgn = (h < 4) ? -1.0f : 1.0f;

    const float* q  = g_qkv + 0 * DD * TT + c  * TT;
    const float* qp = g_qkv + 0 * DD * TT + pc * TT;
    const float* k  = g_qkv + 1 * DD * TT + c  * TT;
    const float* kp = g_qkv + 1 * DD * TT + pc * TT;
    const float* v  = g_qkv + 2 * DD * TT + c  * TT;

    __shared__ float ks[512];
    __shared__ float vs[512];
    __shared__ float cs[512];
    __shared__ float sn[512];
    __shared__ float s_invf;

    const int tid = threadIdx.x;
    if (tid == 0) s_invf = (float)pow(10000.0, -(double)(2 * fi) / 64.0);
    __syncthreads();
    const float invf = s_invf;

#pragma unroll
    for (int off = 0; off < 512; off += 256) {
        const int tt = tid + off;
        float sv, cv;
        sincosf((float)tt * invf, &sv, &cv);
        cs[tt] = cv;
        sn[tt] = sv;
        ks[tt] = k[tt] * cv + sgn * kp[tt] * sv;
        vs[tt] = v[tt];
    }
    __syncthreads();

#pragma unroll
    for (int rep = 0; rep < 2; rep++) {
        const int i = rep ? (511 - tid) : tid;
        const float qr = q[i] * cs[i] + sgn * qp[i] * sn[i];
        const float qs = qr * (0.125f * LOG2E);
        float l = 0.f, acc = 0.f;
#pragma unroll 4
        for (int j = 0; j <= i; j++) {
            float p = fast_ex2(qs * ks[j]);
            l += p;
            acc += p * vs[j];
        }
        g_ao[c * TT + i] = acc / l;
    }
}

// ---------------------------------------------------------------------------
// Transpose + split ao: g_ao[d][t] fp32 -> gaoT{hi,lo}[t][d] bf16
// ---------------------------------------------------------------------------
__global__ void __launch_bounds__(256) transpose_split_kernel() {
    __shared__ float tile[32][33];
    const int tx = threadIdx.x;   // 0..31
    const int ty = threadIdx.y;   // 0..7
    const int d0 = blockIdx.y * 32;
    const int t0 = blockIdx.x * 32;

#pragma unroll
    for (int i = 0; i < 4; i++)
        tile[ty + i * 8][tx] = g_ao[(d0 + ty + i * 8) * 512 + t0 + tx];
    __syncthreads();

#pragma unroll
    for (int i = 0; i < 4; i++) {
        const int r = ty + i * 8;
        const float v = tile[tx][r];
        const __nv_bfloat16 h = __float2bfloat16(v);
        gaoThi[(t0 + r) * 512 + d0 + tx] = h;
        gaoTlo[(t0 + r) * 512 + d0 + tx] =
            __float2bfloat16(v - __bfloat162float(h));
    }
}

// ---------------------------------------------------------------------------
extern "C" void kernel_launch(void* const* d_in, const int* in_sizes, int n_in,
                              void* d_out, int out_size) {
    const float* x  = (const float*)d_in[0];
    const float* Wq = (const float*)d_in[1];
    const float* Wk = (const float*)d_in[2];
    const float* Wv = (const float*)d_in[3];
    const float* Wo = (const float*)d_in[4];
    float* y = (float*)d_out;

    static int configured = 0;
    if (!configured) {
        cudaFuncSetAttribute(gemm1_kernel,
                             cudaFuncAttributeMaxDynamicSharedMemorySize, GEMM_SMEM);
        cudaFuncSetAttribute(gemm2_kernel,
                             cudaFuncAttributeMaxDynamicSharedMemorySize, GEMM_SMEM);
        configured = 1;
    }

    split_kernel<<<1280, 256>>>((const float4*)x, (const float4*)Wq,
                                (const float4*)Wk, (const float4*)Wv,
                                (const float4*)Wo);
    gemm1_kernel<<<dim3(24, 8), 128, GEMM_SMEM>>>();
    attn_kernel<<<512, 256>>>();
    transpose_split_kernel<<<dim3(16, 16), dim3(32, 8)>>>();
    gemm2_kernel<<<dim3(8, 8), 128, GEMM_SMEM>>>(y);
}